// round 2
// baseline (speedup 1.0000x reference)
#include <cuda_runtime.h>
#include <cuda_bf16.h>
#include <stdint.h>

// Problem dims (fixed by the dataset)
#define NBATCH 4
#define NROWS  8192
#define DMEM   128
#define NTILES 64           // 8192 / 128 j-tiles
#define JSPLIT 4            // j-range split per i-tile
#define NJ     (NTILES / JSPLIT)
#define TILEB  32768        // 128 rows * 128 bf16 * 2B
#define THRESH 0.65f

// Scratch (device globals are the sanctioned scratch mechanism)
__device__ __align__(16) __nv_bfloat16 g_proj[(size_t)NBATCH * NROWS * DMEM]; // 8 MB normalized proj
__device__ float g_deg[NBATCH * NROWS];   // off-diagonal hit count per row

// ---------------------------------------------------------------------------
// PTX helpers (arch-portable: ldmatrix + mma.sync, sm_80+)
// ---------------------------------------------------------------------------
__device__ __forceinline__ uint32_t su32(const void* p) {
    uint32_t a;
    asm("{ .reg .u64 t; cvta.to.shared.u64 t, %1; cvt.u32.u64 %0, t; }" : "=r"(a) : "l"(p));
    return a;
}

#define LDMATRIX_X4(r0, r1, r2, r3, addr) \
    asm volatile("ldmatrix.sync.aligned.m8n8.x4.shared.b16 {%0,%1,%2,%3}, [%4];" \
                 : "=r"(r0), "=r"(r1), "=r"(r2), "=r"(r3) : "r"(addr))

#define MMA_BF16(d, a, b0, b1) \
    asm volatile("mma.sync.aligned.m16n8k16.row.col.f32.bf16.bf16.f32 " \
                 "{%0,%1,%2,%3}, {%4,%5,%6,%7}, {%8,%9}, {%0,%1,%2,%3};" \
                 : "+f"((d)[0]), "+f"((d)[1]), "+f"((d)[2]), "+f"((d)[3]) \
                 : "r"((a)[0]), "r"((a)[1]), "r"((a)[2]), "r"((a)[3]), "r"(b0), "r"(b1))

// Copy one 128x128 bf16 tile (32KB) gmem->smem with a 16B-chunk XOR swizzle
// (chunk c of row r lands at chunk c^(r&7)) so ldmatrix 8-row groups are
// bank-conflict-free. 256 threads x 8 cp.async of 16B.
__device__ __forceinline__ void copy_tile(uint32_t dst, const __nv_bfloat16* src, int tid) {
    #pragma unroll
    for (int k = 0; k < 8; k++) {
        int idx = tid + k * 256;             // 2048 16B chunks
        int r = idx >> 4, c = idx & 15;
        uint32_t doff = (uint32_t)(r * 256 + ((c ^ (r & 7)) << 4));
        asm volatile("cp.async.cg.shared.global [%0], [%1], 16;"
                     :: "r"(dst + doff), "l"((const char*)src + (size_t)idx * 16) : "memory");
    }
}

// ---------------------------------------------------------------------------
// Stage 1: proj = normalize(x @ W^T + b) -> bf16 row-major. Also zeroes g_deg.
// 128 threads, 64 rows per CTA, 8x8 register tiles, exact fp32 math.
// ---------------------------------------------------------------------------
__global__ void __launch_bounds__(128) proj_kernel(const float* __restrict__ X,
                                                   const float* __restrict__ W,
                                                   const float* __restrict__ Bv) {
    extern __shared__ float sm[];
    float* Ws   = sm;                 // [128][129] transposed: Ws[d*129+o] = W[o][d]
    float* Xs   = Ws + 128 * 129;     // [64][129]
    float* bs   = Xs + 64 * 129;      // [128]
    float* part = bs + 128;           // [64][16]
    float* rn   = part + 64 * 16;     // [64]

    int tid = threadIdx.x;
    int tr = tid & 7, tc = tid >> 3;
    int r0 = blockIdx.x * 64;

    if (blockIdx.x < 256) g_deg[blockIdx.x * 128 + tid] = 0.0f;

    for (int idx = tid; idx < 128 * 128; idx += 128) {
        int o = idx >> 7, d = idx & 127;
        Ws[d * 129 + o] = W[idx];
    }
    for (int idx = tid; idx < 64 * 128; idx += 128) {
        int r = idx >> 7, d = idx & 127;
        Xs[r * 129 + d] = X[(size_t)(r0 + r) * 128 + d];
    }
    bs[tid] = Bv[tid];
    __syncthreads();

    float acc[8][8];
    #pragma unroll
    for (int i = 0; i < 8; i++)
        #pragma unroll
        for (int j = 0; j < 8; j++) acc[i][j] = 0.f;

    #pragma unroll 4
    for (int d = 0; d < 128; d++) {
        float xv[8], wv[8];
        #pragma unroll
        for (int i = 0; i < 8; i++) xv[i] = Xs[(tr * 8 + i) * 129 + d];
        #pragma unroll
        for (int j = 0; j < 8; j++) wv[j] = Ws[d * 129 + tc * 8 + j];
        #pragma unroll
        for (int i = 0; i < 8; i++)
            #pragma unroll
            for (int j = 0; j < 8; j++) acc[i][j] += xv[i] * wv[j];
    }

    #pragma unroll
    for (int i = 0; i < 8; i++) {
        float p = 0.f;
        #pragma unroll
        for (int j = 0; j < 8; j++) {
            acc[i][j] += bs[tc * 8 + j];
            p += acc[i][j] * acc[i][j];
        }
        part[(tr * 8 + i) * 16 + tc] = p;
    }
    __syncthreads();
    if (tid < 64) {
        float s = 0.f;
        #pragma unroll
        for (int k = 0; k < 16; k++) s += part[tid * 16 + k];
        rn[tid] = 1.0f / fmaxf(sqrtf(s), 1e-12f);
    }
    __syncthreads();

    #pragma unroll
    for (int i = 0; i < 8; i++) {
        int r = tr * 8 + i;
        float sc = rn[r];
        uint32_t pk[4];
        #pragma unroll
        for (int q = 0; q < 4; q++) {
            __nv_bfloat162 h = __floats2bfloat162_rn(acc[i][2 * q] * sc, acc[i][2 * q + 1] * sc);
            pk[q] = *reinterpret_cast<uint32_t*>(&h);
        }
        *reinterpret_cast<uint4*>(g_proj + (size_t)(r0 + r) * DMEM + tc * 8) =
            make_uint4(pk[0], pk[1], pk[2], pk[3]);
    }
}

// ---------------------------------------------------------------------------
// Stage 2: sim tile GEMM (P P^T) via mma.sync bf16; threshold in registers.
// CTA: 256 threads = 4 m-warps (32 rows each) x 2 n-warps (64 cols each).
// Grid: NBATCH * 64 i-tiles * JSPLIT. Accumulators live in registers; hits
// (sim > 0.65, j != i) are ~zero-probability and handled atomically.
// ---------------------------------------------------------------------------
__global__ void __launch_bounds__(256, 2) sim_kernel(const float* __restrict__ X,
                                                     float* __restrict__ out) {
    extern __shared__ unsigned char dsm[];
    uint32_t smA  = su32(dsm);
    uint32_t smB0 = smA + TILEB;
    uint32_t smB1 = smA + 2 * TILEB;

    int tid = threadIdx.x, wid = tid >> 5, l = tid & 31;
    int wm = wid >> 1, wn = wid & 1;         // m-warp (rows wm*32..+31), n-half

    int bid = blockIdx.x;
    int batch = bid >> 8;
    int it    = (bid >> 2) & 63;
    int j0    = (bid & 3) * NJ;

    const __nv_bfloat16* pb = g_proj + (size_t)batch * NROWS * DMEM;
    const float* Xb = X + (size_t)batch * NROWS * DMEM;
    float* outb = out + (size_t)batch * NROWS * DMEM;
    float* degb = g_deg + batch * NROWS;

    // Prologue: A tile + first two B tiles
    copy_tile(smA, pb + (size_t)it * 128 * DMEM, tid);
    copy_tile(smB0, pb + (size_t)j0 * 128 * DMEM, tid);
    asm volatile("cp.async.commit_group;" ::: "memory");
    copy_tile(smB1, pb + (size_t)(j0 + 1) * 128 * DMEM, tid);
    asm volatile("cp.async.commit_group;" ::: "memory");
    asm volatile("cp.async.wait_group 1;" ::: "memory");
    __syncthreads();

    // Resident A fragments: 2 m16-frags x 8 k-steps x 4 regs = 64 regs
    uint32_t a[2][8][4];
    #pragma unroll
    for (int m = 0; m < 2; m++)
        #pragma unroll
        for (int k = 0; k < 8; k++) {
            int r = wm * 32 + m * 16 + (l & 15);
            int chunk = k * 2 + ((l >> 4) & 1);
            uint32_t addr = smA + r * 256 + ((chunk ^ (r & 7)) << 4);
            LDMATRIX_X4(a[m][k][0], a[m][k][1], a[m][k][2], a[m][k][3], addr);
        }

    for (int jt = j0; jt < j0 + NJ; jt++) {
        uint32_t smB = ((jt - j0) & 1) ? smB1 : smB0;

        #pragma unroll 1
        for (int g = 0; g < 4; g++) {
            int n0 = wn * 64 + g * 16;
            float d[2][2][4];
            #pragma unroll
            for (int m = 0; m < 2; m++)
                #pragma unroll
                for (int h = 0; h < 2; h++)
                    #pragma unroll
                    for (int p = 0; p < 4; p++) d[m][h][p] = 0.f;

            #pragma unroll
            for (int k = 0; k < 8; k++) {
                int nn = n0 + (l & 7) + ((l & 16) ? 8 : 0);
                int chunk = k * 2 + ((l >> 3) & 1);
                uint32_t addr = smB + nn * 256 + ((chunk ^ (nn & 7)) << 4);
                uint32_t b0, b1, b2, b3;
                LDMATRIX_X4(b0, b1, b2, b3, addr);
                #pragma unroll
                for (int m = 0; m < 2; m++) {
                    MMA_BF16(d[m][0], a[m][k], b0, b1);
                    MMA_BF16(d[m][1], a[m][k], b2, b3);
                }
            }

            // Fast path: max-tree over this lane's 16 values, one ballot.
            float vmax = d[0][0][0];
            #pragma unroll
            for (int m = 0; m < 2; m++)
                #pragma unroll
                for (int h = 0; h < 2; h++)
                    #pragma unroll
                    for (int p = 0; p < 4; p++) vmax = fmaxf(vmax, d[m][h][p]);
            unsigned warp_any = __ballot_sync(0xffffffffu, vmax > THRESH);

            if (warp_any) {   // rare: diagonal tile (skipped) or a true hit
                #pragma unroll
                for (int m = 0; m < 2; m++)
                    #pragma unroll
                    for (int h = 0; h < 2; h++)
                        #pragma unroll
                        for (int p = 0; p < 4; p++) {
                            unsigned msk = __ballot_sync(0xffffffffu, d[m][h][p] > THRESH);
                            while (msk) {
                                int b = __ffs(msk) - 1; msk &= msk - 1;
                                int ib = it * 128 + wm * 32 + m * 16 + (b >> 2) + ((p & 2) ? 8 : 0);
                                int jb = jt * 128 + n0 + h * 8 + ((b & 3) << 1) + (p & 1);
                                if (ib != jb) {   // diagonal handled analytically
                                    float4 xv = reinterpret_cast<const float4*>(Xb + (size_t)jb * DMEM)[l];
                                    float* orow = outb + (size_t)ib * DMEM + l * 4;
                                    atomicAdd(orow + 0, xv.x);
                                    atomicAdd(orow + 1, xv.y);
                                    atomicAdd(orow + 2, xv.z);
                                    atomicAdd(orow + 3, xv.w);
                                    if (l == 0) atomicAdd(&degb[ib], 1.0f);
                                }
                            }
                        }
            }
        }

        __syncthreads();                                   // everyone done with smB
        if (jt + 2 < j0 + NJ)
            copy_tile(smB, pb + (size_t)(jt + 2) * 128 * DMEM, tid);
        asm volatile("cp.async.commit_group;" ::: "memory");
        asm volatile("cp.async.wait_group 1;" ::: "memory"); // next B landed
        __syncthreads();
    }
}

// ---------------------------------------------------------------------------
// Stage 3: out[i] = (hits[i] + X[i]) / (1 + deg_hits[i])   (diagonal folded in)
// ---------------------------------------------------------------------------
__global__ void __launch_bounds__(256) fin_kernel(const float* __restrict__ X,
                                                  float* __restrict__ out) {
    size_t v = (size_t)blockIdx.x * 256 + threadIdx.x;   // float4 index
    int row = (int)(v >> 5);                             // 32 float4 per row
    float inv = 1.0f / (1.0f + g_deg[row]);
    float4 o = reinterpret_cast<float4*>(out)[v];
    float4 x = reinterpret_cast<const float4*>(X)[v];
    o.x = (o.x + x.x) * inv; o.y = (o.y + x.y) * inv;
    o.z = (o.z + x.z) * inv; o.w = (o.w + x.w) * inv;
    reinterpret_cast<float4*>(out)[v] = o;
}

// ---------------------------------------------------------------------------
extern "C" void kernel_launch(void* const* d_in, const int* in_sizes, int n_in,
                              void* d_out, int out_size) {
    (void)in_sizes; (void)n_in; (void)out_size;
    const float* X  = (const float*)d_in[0];
    const float* W  = (const float*)d_in[1];
    const float* Bv = (const float*)d_in[2];
    float* out = (float*)d_out;

    const int PROJ_SMEM = (128 * 129 + 64 * 129 + 128 + 64 * 16 + 64) * 4; // ~102 KB
    const int SIM_SMEM  = 3 * TILEB;                                        // 96 KB
    cudaFuncSetAttribute(proj_kernel, cudaFuncAttributeMaxDynamicSharedMemorySize, PROJ_SMEM);
    cudaFuncSetAttribute(sim_kernel,  cudaFuncAttributeMaxDynamicSharedMemorySize, SIM_SMEM);

    cudaMemsetAsync(d_out, 0, sizeof(float) * (size_t)NBATCH * NROWS * DMEM, 0);

    proj_kernel<<<(NBATCH * NROWS) / 64, 128, PROJ_SMEM>>>(X, W, Bv);
    sim_kernel<<<NBATCH * 64 * JSPLIT, 256, SIM_SMEM>>>(X, out);
    fin_kernel<<<(NBATCH * NROWS * DMEM / 4) / 256, 256>>>(X, out);
}